// round 3
// baseline (speedup 1.0000x reference)
#include <cuda_runtime.h>
#include <cstdint>

// Device-global state (no allocation allowed in kernel_launch).
__device__ double             g_loss_acc;
__device__ unsigned long long g_correct_acc;
__device__ int                g_labels_are_i32;

static constexpr int C  = 1000;
static constexpr int C4 = C / 4;          // 250 float4 per row
static constexpr int WARPS_PER_BLOCK = 8; // 256 threads

// Probe: detect label dtype (int32 vs int64) + zero accumulators.
// If the buffer is int32 [0,1000), int64-interpretation fuses adjacent labels
// -> values >= 2^32 with overwhelming probability over 256 samples.
__global__ void msrp_probe_init_kernel(const void* labels_raw, int B) {
    g_loss_acc = 0.0;
    g_correct_acc = 0ull;
    const long long* l64 = (const long long*)labels_raw;
    int n = B < 256 ? B : 256;
    int is_i32 = 0;
    for (int i = 0; i < n; ++i) {
        long long v = l64[i];
        if (v < 0 || v >= (long long)C) { is_i32 = 1; break; }
    }
    g_labels_are_i32 = is_i32;
}

__global__ __launch_bounds__(256) void msrp_main_kernel(
    const float* __restrict__ outs,
    const void*  __restrict__ labels_raw,
    int B)
{
    const int warp_in_block = threadIdx.x >> 5;
    const int lane = threadIdx.x & 31;
    const int row  = blockIdx.x * WARPS_PER_BLOCK + warp_in_block;

    __shared__ float s_loss[WARPS_PER_BLOCK];
    __shared__ int   s_corr[WARPS_PER_BLOCK];

    float warp_loss = 0.0f;
    int   warp_corr = 0;

    if (row < B) {
        int label;
        if (g_labels_are_i32) label = ((const int*)labels_raw)[row];
        else                  label = (int)((const long long*)labels_raw)[row];
        // Defensive clamp: a wrong dtype guess shows up as rel_err, not a crash.
        if ((unsigned)label >= (unsigned)C) label = 0;

        const float* rowp = outs + (size_t)row * C;
        // Broadcast load of the ground-truth score (same addr all lanes -> 1 txn)
        const float ground = __ldg(rowp + label);
        const float c = 1.0f - ground;   // margin = max(0, x + c)

        const float4* row4 = reinterpret_cast<const float4*>(rowp);

        float sum  = 0.0f;
        float vmax = -3.402823466e+38f;
        int   imax = 0x7FFFFFFF;

        #pragma unroll 4
        for (int i = lane; i < C4; i += 32) {
            float4 v = row4[i];
            sum += fmaxf(v.x + c, 0.0f);
            sum += fmaxf(v.y + c, 0.0f);
            sum += fmaxf(v.z + c, 0.0f);
            sum += fmaxf(v.w + c, 0.0f);
            const int base = i * 4;
            // strict > keeps first occurrence within a lane (ascending index order)
            if (v.x > vmax) { vmax = v.x; imax = base;     }
            if (v.y > vmax) { vmax = v.y; imax = base + 1; }
            if (v.z > vmax) { vmax = v.z; imax = base + 2; }
            if (v.w > vmax) { vmax = v.w; imax = base + 3; }
        }

        // Warp reduction: hinge sum
        #pragma unroll
        for (int off = 16; off > 0; off >>= 1)
            sum += __shfl_down_sync(0xFFFFFFFFu, sum, off);

        // Warp reduction: argmax, smallest-index tie-break (first occurrence)
        #pragma unroll
        for (int off = 16; off > 0; off >>= 1) {
            float ov = __shfl_down_sync(0xFFFFFFFFu, vmax, off);
            int   oi = __shfl_down_sync(0xFFFFFFFFu, imax, off);
            if (ov > vmax || (ov == vmax && oi < imax)) { vmax = ov; imax = oi; }
        }

        if (lane == 0) {
            warp_loss = sum;                     // includes the j==label "+1" term
            warp_corr = (imax == label) ? 1 : 0;
        }
    }

    if (lane == 0) {
        s_loss[warp_in_block] = warp_loss;
        s_corr[warp_in_block] = warp_corr;
    }
    __syncthreads();

    if (threadIdx.x == 0) {
        float bl = 0.0f;
        int   bc = 0;
        #pragma unroll
        for (int w = 0; w < WARPS_PER_BLOCK; ++w) { bl += s_loss[w]; bc += s_corr[w]; }
        atomicAdd(&g_loss_acc, (double)bl);
        atomicAdd(&g_correct_acc, (unsigned long long)bc);
    }
}

__global__ void msrp_finalize_kernel(float* out, int B, int out_size) {
    // loss = (sum_all_margins - B) / B  because j==label contributes exactly 1/row
    if (out_size >= 1) out[0] = (float)(g_loss_acc / (double)B - 1.0);
    if (out_size >= 2) out[1] = (float)g_correct_acc;
}

extern "C" void kernel_launch(void* const* d_in, const int* in_sizes, int n_in,
                              void* d_out, int out_size) {
    // Identify inputs by size, not position: outputs has B*C elements, labels has B.
    int oi = 0, li = 1;
    if (in_sizes[1] > in_sizes[0]) { oi = 1; li = 0; }
    const float* outs   = (const float*)d_in[oi];
    const void*  labels = d_in[li];
    const int B = in_sizes[li];

    float* out = (float*)d_out;

    msrp_probe_init_kernel<<<1, 1>>>(labels, B);
    const int blocks = (B + WARPS_PER_BLOCK - 1) / WARPS_PER_BLOCK;
    msrp_main_kernel<<<blocks, 256>>>(outs, labels, B);
    msrp_finalize_kernel<<<1, 1>>>(out, B, out_size);
}

// round 5
// speedup vs baseline: 1.2256x; 1.2256x over previous
#include <cuda_runtime.h>
#include <cstdint>
#include <cfloat>

// Device-global state (no allocation allowed in kernel_launch).
__device__ double             g_loss_acc;
__device__ unsigned long long g_correct_acc;
__device__ unsigned int       g_blocks_done;
__device__ int                g_labels_are_i32;

static constexpr int C  = 1000;
static constexpr int C4 = C / 4;          // 250 float4 per row
static constexpr int WARPS_PER_BLOCK = 8; // 256 threads
static constexpr int ROW_ITERS = (C4 + 31) / 32;  // 8

// Probe (parallel): detect label dtype (int32 vs int64) + zero accumulators.
// If the buffer is int32 with values in [0,1000), an int64 interpretation fuses
// adjacent labels -> values >= 2^32 with overwhelming probability over 256 rows.
__global__ void msrp_probe_init_kernel(const void* labels_raw, int B) {
    __shared__ int s_bad;
    if (threadIdx.x == 0) {
        s_bad = 0;
        g_loss_acc    = 0.0;
        g_correct_acc = 0ull;
        g_blocks_done = 0u;
    }
    __syncthreads();
    const int n = B < 256 ? B : 256;
    if ((int)threadIdx.x < n) {
        long long v = ((const long long*)labels_raw)[threadIdx.x];
        if (v < 0 || v >= (long long)C) s_bad = 1;   // benign race, all write 1
    }
    __syncthreads();
    if (threadIdx.x == 0) g_labels_are_i32 = s_bad;
}

__global__ __launch_bounds__(256) void msrp_main_kernel(
    const float* __restrict__ outs,
    const void*  __restrict__ labels_raw,
    float* __restrict__ out,
    int B, int out_size)
{
    const int warp_in_block = threadIdx.x >> 5;
    const int lane = threadIdx.x & 31;
    const int row  = blockIdx.x * WARPS_PER_BLOCK + warp_in_block;

    __shared__ float s_loss[WARPS_PER_BLOCK];
    __shared__ int   s_corr[WARPS_PER_BLOCK];

    float warp_loss = 0.0f;
    int   warp_corr = 0;

    if (row < B) {
        int label;
        if (g_labels_are_i32) label = ((const int*)labels_raw)[row];
        else                  label = (int)((const long long*)labels_raw)[row];
        if ((unsigned)label >= (unsigned)C) label = 0;   // never crash; err shows as rel_err

        const float*  rowp = outs + (size_t)row * C;
        const float4* row4 = reinterpret_cast<const float4*>(rowp);

        // Broadcast load of the ground-truth score (same addr all lanes -> 1 txn)
        const float ground = __ldg(rowp + label);
        const float c = 1.0f - ground;   // margin = max(0, x + c)

        // Front-batched streaming loads: 8 outstanding LDG.128 per thread.
        float4 v[ROW_ITERS];
        #pragma unroll
        for (int it = 0; it < ROW_ITERS; ++it) {
            const int i = lane + it * 32;
            if (i < C4) {
                v[it] = __ldcs(&row4[i]);   // evict-first: 262MB read-once >> L2
            } else {
                v[it] = make_float4(-FLT_MAX, -FLT_MAX, -FLT_MAX, -FLT_MAX);
            }
        }

        float sum  = 0.0f;
        float vmax = -FLT_MAX;
        int   imax = 0x7FFFFFFF;

        #pragma unroll
        for (int it = 0; it < ROW_ITERS; ++it) {
            const int base = (lane + it * 32) * 4;
            sum += fmaxf(v[it].x + c, 0.0f);
            sum += fmaxf(v[it].y + c, 0.0f);
            sum += fmaxf(v[it].z + c, 0.0f);
            sum += fmaxf(v[it].w + c, 0.0f);
            // strict > keeps first occurrence within a lane (ascending index order)
            if (v[it].x > vmax) { vmax = v[it].x; imax = base;     }
            if (v[it].y > vmax) { vmax = v[it].y; imax = base + 1; }
            if (v[it].z > vmax) { vmax = v[it].z; imax = base + 2; }
            if (v[it].w > vmax) { vmax = v[it].w; imax = base + 3; }
        }

        // Warp reduction: hinge sum
        #pragma unroll
        for (int off = 16; off > 0; off >>= 1)
            sum += __shfl_down_sync(0xFFFFFFFFu, sum, off);

        // Warp reduction: argmax, smallest-index tie-break (first occurrence)
        #pragma unroll
        for (int off = 16; off > 0; off >>= 1) {
            float ov = __shfl_down_sync(0xFFFFFFFFu, vmax, off);
            int   oi = __shfl_down_sync(0xFFFFFFFFu, imax, off);
            if (ov > vmax || (ov == vmax && oi < imax)) { vmax = ov; imax = oi; }
        }

        if (lane == 0) {
            warp_loss = sum;                     // includes the j==label "+1" term
            warp_corr = (imax == label) ? 1 : 0;
        }
    }

    if (lane == 0) {
        s_loss[warp_in_block] = warp_loss;
        s_corr[warp_in_block] = warp_corr;
    }
    __syncthreads();

    if (threadIdx.x == 0) {
        float bl = 0.0f;
        int   bc = 0;
        #pragma unroll
        for (int w = 0; w < WARPS_PER_BLOCK; ++w) { bl += s_loss[w]; bc += s_corr[w]; }
        atomicAdd(&g_loss_acc, (double)bl);
        atomicAdd(&g_correct_acc, (unsigned long long)bc);

        // Fused finalize: last block to finish writes the outputs.
        __threadfence();
        unsigned done = atomicAdd(&g_blocks_done, 1u);
        if (done == gridDim.x - 1) {
            __threadfence();
            // loss = (sum_all_margins - B) / B : j==label contributes exactly 1/row
            if (out_size >= 1) out[0] = (float)(g_loss_acc / (double)B - 1.0);
            if (out_size >= 2) out[1] = (float)g_correct_acc;
        }
    }
}

extern "C" void kernel_launch(void* const* d_in, const int* in_sizes, int n_in,
                              void* d_out, int out_size) {
    // Identify inputs by size, not position: outputs has B*C elements, labels has B.
    int oi = 0, li = 1;
    if (in_sizes[1] > in_sizes[0]) { oi = 1; li = 0; }
    const float* outs   = (const float*)d_in[oi];
    const void*  labels = d_in[li];
    const int B = in_sizes[li];

    msrp_probe_init_kernel<<<1, 256>>>(labels, B);
    const int blocks = (B + WARPS_PER_BLOCK - 1) / WARPS_PER_BLOCK;
    msrp_main_kernel<<<blocks, 256>>>(outs, labels, (float*)d_out, B, out_size);
}